// round 17
// baseline (speedup 1.0000x reference)
#include <cuda_runtime.h>
#include <cuda_bf16.h>

// Problem constants
#define PB    32    // batch
#define NN    8     // objects
#define P0    64
#define P1    128
#define P2    64
#define CC    128   // channels
#define KK    56    // permutations of (8,2)
#define NT    1024  // threads: 8 subgroups x 128 channels
#define GRID  145   // 112 binary(merged) + 32 unary + 1 nullary (single wave)

// Scratch (allocation-free: __device__ globals)
__device__ float g_N0[PB * CC];
__device__ float g_U0[PB * NN * CC];
__device__ float g_U1[PB * NN * CC];
__device__ float g_Bm[PB * KK * CC];   // min(slot0, slot1) per (b, perm k, c)
// 8 arrive counters, each on its own 128B line (stride 32 ints).
__device__ int   g_arr[8 * 32];
__device__ int   g_done;

// HW tanh: single MUFU op (abs err ~1e-4, inside the 1e-3 gate).
__device__ __forceinline__ float tanh_hw(float x) {
    float r;
    asm("tanh.approx.f32 %0, %1;" : "=f"(r) : "f"(x));
    return r;
}

// 4 weighted-truth FMAs as 2 packed fma.rn.f32x2 + tree min, folded into acc.
// x arrives pre-packed from an LDS.128 register pair (no pack movs).
__device__ __forceinline__ float wt_min4(float acc, ulonglong2 xv,
                                         const unsigned long long* t2,
                                         const unsigned long long* q2, int p) {
    unsigned long long w01, w23;
    asm("fma.rn.f32x2 %0, %1, %2, %3;" : "=l"(w01) : "l"(xv.x), "l"(t2[p]),     "l"(q2[p]));
    asm("fma.rn.f32x2 %0, %1, %2, %3;" : "=l"(w23) : "l"(xv.y), "l"(t2[p + 1]), "l"(q2[p + 1]));
    float w0, w1, w2, w3;
    asm("mov.b64 {%0, %1}, %2;" : "=f"(w0), "=f"(w1) : "l"(w01));
    asm("mov.b64 {%0, %1}, %2;" : "=f"(w2), "=f"(w3) : "l"(w23));
    return fminf(acc, fminf(fminf(w0, w1), fminf(w2, w3)));
}

// Compute 16 (t, q) pairs from kr[16] into packed f32x2 registers.
__device__ __forceinline__ void make_tq(const float* kr,
                                        unsigned long long* t2,
                                        unsigned long long* q2) {
    #pragma unroll
    for (int p = 0; p < 8; p++) {
        const float ta = tanh_hw(kr[2 * p]);
        const float tb = tanh_hw(kr[2 * p + 1]);
        const float qa = fmaf(-ta, ta, 1.0f);
        const float qb = fmaf(-tb, tb, 1.0f);
        asm("mov.b64 %0, {%1, %2};" : "=l"(t2[p]) : "f"(ta), "f"(tb));
        asm("mov.b64 %0, {%1, %2};" : "=l"(q2[p]) : "f"(qa), "f"(qb));
    }
}

__global__ __launch_bounds__(NT) void fused_k(const float* __restrict__ nullary,
                                              const float* __restrict__ unary,
                                              const float* __restrict__ binary,
                                              const float* __restrict__ kern,
                                              float* __restrict__ out) {
    __shared__ __align__(16) float xs[2048];   // 8 KB  x staging
    __shared__ __align__(16) float buf[8192];  // 32 KB reduction buffer

    const int blk = blockIdx.x;
    const int tid = threadIdx.x;
    const int u   = tid >> 7;     // subgroup 0..7
    const int c   = tid & 127;    // channel
    const ulonglong2* xsu = reinterpret_cast<const ulonglong2*>(xs);
    float4* xs4w = reinterpret_cast<float4*>(xs);

    // ================= Phase 1: slot-partial mins =================
    if (blk < 112) {
        // ---- merged binary: one perm k = blk>>1, b-half = blk&1.
        //      subgroup u spans the 128 combined t-rows (slot0: u<4, slot1: u>=4).
        const int m     = blk >> 1;
        const int bh    = blk & 1;
        const int bbase = bh * 16;
        const int i     = m / 7;
        const int jp    = m % 7;
        const int j     = jp + (jp >= i);
        const int ip    = i - (i > j);
        const int tbase = 320 + u * 16;       // rows 320..447 across subgroups

        // 1) kern loads first (latency covered by staging)
        float kr[16];
        #pragma unroll
        for (int ff = 0; ff < 16; ff++) kr[ff] = kern[(tbase + ff) * CC + c];

        // 2) x staging: [slot][b16][64f] = 512 float4
        if (tid < 512) {
            const int slot = tid >> 8, b16 = (tid >> 4) & 15, f4 = tid & 15;
            const int b = bbase + b16;
            const long off = slot
                ? ((long)(b * NN + j) * (NN - 1) + ip) * P2
                : ((long)(b * NN + i) * (NN - 1) + jp) * P2;
            xs4w[tid] = *reinterpret_cast<const float4*>(binary + off + f4 * 4);
        }

        // 3) tanh -> packed (t, q)
        unsigned long long t2[8], q2[8];
        make_tq(kr, t2, q2);
        __syncthreads();

        float a[16];
        #pragma unroll
        for (int b = 0; b < 16; b++) a[b] = 1e30f;

        const int xbase = (u >> 2) * 256;     // slot block (16 b x 16 float4)
        const int fo    = (u & 3) * 4;        // f-chunk within slot
        #pragma unroll
        for (int b = 0; b < 16; b++) {
            #pragma unroll
            for (int v = 0; v < 4; v++)
                a[b] = wt_min4(a[b], xsu[xbase + b * 16 + fo + v], t2, q2, 2 * v);
        }

        // reduce 8 chunks -> 1 (3 rounds)
        if (u >= 4) {
            #pragma unroll
            for (int b = 0; b < 16; b++)
                buf[((u - 4) * 16 + b) * 128 + c] = a[b];
        }
        __syncthreads();
        if (u < 4) {
            #pragma unroll
            for (int b = 0; b < 16; b++)
                a[b] = fminf(a[b], buf[(u * 16 + b) * 128 + c]);
        }
        __syncthreads();
        if (u == 2 || u == 3) {
            #pragma unroll
            for (int b = 0; b < 16; b++)
                buf[((u - 2) * 16 + b) * 128 + c] = a[b];
        }
        __syncthreads();
        if (u < 2) {
            #pragma unroll
            for (int b = 0; b < 16; b++)
                a[b] = fminf(a[b], buf[(u * 16 + b) * 128 + c]);
        }
        __syncthreads();
        if (u == 1) {
            #pragma unroll
            for (int b = 0; b < 16; b++)
                buf[b * 128 + c] = a[b];
        }
        __syncthreads();
        if (u == 0) {
            #pragma unroll
            for (int b = 0; b < 16; b++) {
                const float r = fminf(a[b], buf[b * 128 + c]);
                g_Bm[((bbase + b) * KK + m) * CC + c] = r;
            }
        }

    } else if (blk < 144) {
        // ---- unary slots: one (i, slot, b-half16); 8 f-chunks of 16 f ----
        const int  r     = blk - 112;
        const bool slot1 = (r >= 16);
        const int  rr    = r & 15;
        const int  i     = rr >> 1;
        const int  b0    = (rr & 1) * 16;
        const int  tbase = (slot1 ? 192 : 64) + u * 16;

        float kr[16];
        #pragma unroll
        for (int ff = 0; ff < 16; ff++) kr[ff] = kern[(tbase + ff) * CC + c];

        if (tid < 512) {
            const int b = tid >> 5, f4 = tid & 31;
            xs4w[tid] = *reinterpret_cast<const float4*>(
                unary + ((b0 + b) * NN + i) * P1 + f4 * 4);
        }

        unsigned long long t2[8], q2[8];
        make_tq(kr, t2, q2);
        __syncthreads();

        float a[16];
        #pragma unroll
        for (int b = 0; b < 16; b++) a[b] = 1e30f;

        #pragma unroll
        for (int b = 0; b < 16; b++) {
            #pragma unroll
            for (int v = 0; v < 4; v++)
                a[b] = wt_min4(a[b], xsu[b * 16 + u * 2 + (v >> 1) * 1 + 0 + ((u * 4 + v))], t2, q2, 2 * v);
        }
        // NOTE: index rewritten below for clarity -- see corrected loop.

        // (corrected mainloop indexing)
        #pragma unroll
        for (int b = 0; b < 16; b++) a[b] = 1e30f;
        #pragma unroll
        for (int b = 0; b < 16; b++) {
            #pragma unroll
            for (int v = 0; v < 4; v++)
                a[b] = wt_min4(a[b], xsu[b * 32 + u * 4 + v], t2, q2, 2 * v);
        }

        // reduce 8 f-chunks -> 1
        if (u >= 4) {
            #pragma unroll
            for (int b = 0; b < 16; b++)
                buf[((u - 4) * 16 + b) * 128 + c] = a[b];
        }
        __syncthreads();
        if (u < 4) {
            #pragma unroll
            for (int b = 0; b < 16; b++)
                a[b] = fminf(a[b], buf[(u * 16 + b) * 128 + c]);
        }
        __syncthreads();
        if (u == 2 || u == 3) {
            #pragma unroll
            for (int b = 0; b < 16; b++)
                buf[((u - 2) * 16 + b) * 128 + c] = a[b];
        }
        __syncthreads();
        if (u < 2) {
            #pragma unroll
            for (int b = 0; b < 16; b++)
                a[b] = fminf(a[b], buf[(u * 16 + b) * 128 + c]);
        }
        __syncthreads();
        if (u == 1) {
            #pragma unroll
            for (int b = 0; b < 16; b++)
                buf[b * 128 + c] = a[b];
        }
        __syncthreads();
        if (u == 0) {
            float* dst = slot1 ? g_U1 : g_U0;
            #pragma unroll
            for (int b = 0; b < 16; b++) {
                const float rr2 = fminf(a[b], buf[b * 128 + c]);
                dst[((b0 + b) * NN + i) * CC + c] = rr2;
            }
        }

    } else {
        // ---- nullary slot: 32 b x 64 f; subgroup = (f-chunk 16, b-half 16) ----
        const int fh    = u & 3;
        const int bh    = u >> 2;
        const int bbase = bh * 16;
        const int tbase = fh * 16;

        float kr[16];
        #pragma unroll
        for (int ff = 0; ff < 16; ff++) kr[ff] = kern[(tbase + ff) * CC + c];

        if (tid < 512) {
            const int b = tid >> 4, f4 = tid & 15;
            xs4w[tid] = *reinterpret_cast<const float4*>(nullary + b * P0 + f4 * 4);
        }

        unsigned long long t2[8], q2[8];
        make_tq(kr, t2, q2);
        __syncthreads();

        float a[16];
        #pragma unroll
        for (int b = 0; b < 16; b++) a[b] = 1e30f;

        #pragma unroll
        for (int b = 0; b < 16; b++) {
            #pragma unroll
            for (int v = 0; v < 4; v++)
                a[b] = wt_min4(a[b], xsu[(bbase + b) * 16 + fh * 4 + v], t2, q2, 2 * v);
        }

        if (fh >= 2) {
            #pragma unroll
            for (int b = 0; b < 16; b++)
                buf[((bh * 2 + (fh - 2)) * 16 + b) * 128 + c] = a[b];
        }
        __syncthreads();
        if (fh < 2) {
            #pragma unroll
            for (int b = 0; b < 16; b++)
                a[b] = fminf(a[b], buf[((bh * 2 + fh) * 16 + b) * 128 + c]);
        }
        __syncthreads();
        if (fh == 1) {
            #pragma unroll
            for (int b = 0; b < 16; b++)
                buf[((bh * 2) * 16 + b) * 128 + c] = a[b];
        }
        __syncthreads();
        if (fh == 0) {
            #pragma unroll
            for (int b = 0; b < 16; b++) {
                const float r = fminf(a[b], buf[((bh * 2) * 16 + b) * 128 + c]);
                g_N0[(bbase + b) * CC + c] = r;
            }
        }
    }

    // ================= Grid soft-barrier (distributed, 8 padded counters) =========
    __threadfence();
    __syncthreads();
    if (tid == 0) atomicAdd(&g_arr[(blk & 7) << 5], 1);

    if (blk >= PB) return;   // only blocks 0..31 combine

    // 145 blocks: residue 0 gets 19 arrivals, residues 1..7 get 18.
    if (tid < 8) {
        const int target = 18 + (tid == 0 ? 1 : 0);
        while (*((volatile int*)&g_arr[tid << 5]) < target) { }
    }
    __syncthreads();
    __threadfence();

    // ================= Phase 2: combine for batch b = blk =================
    {
        const int b = blk;
        // subgroup u handles k in [7u, 7u+7): i = u constant, j = kk + (kk >= u).
        float bm[7], u1v[7];
        #pragma unroll
        for (int kk = 0; kk < 7; kk++) {
            const int k = u * 7 + kk;
            const int j = kk + (kk >= u);
            bm[kk]  = g_Bm[(b * KK + k) * CC + c];
            u1v[kk] = g_U1[(b * NN + j) * CC + c];
        }
        const float u0v = g_U0[(b * NN + u) * CC + c];

        float mx = -1e30f;
        #pragma unroll
        for (int kk = 0; kk < 7; kk++)
            mx = fmaxf(mx, fminf(bm[kk], u1v[kk]));
        mx = fminf(mx, u0v);          // max_k min(.,U0[u]) == min(max_k ., U0[u])
        buf[u * CC + c] = mx;
        __syncthreads();
        if (tid < CC) {
            float m01 = fmaxf(buf[c],            buf[1 * CC + c]);
            float m23 = fmaxf(buf[2 * CC + c],   buf[3 * CC + c]);
            float m45 = fmaxf(buf[4 * CC + c],   buf[5 * CC + c]);
            float m67 = fmaxf(buf[6 * CC + c],   buf[7 * CC + c]);
            const float mall = fmaxf(fmaxf(m01, m23), fmaxf(m45, m67));
            out[b * CC + c] = fminf(mall, g_N0[b * CC + c]);  // N0 fold (same identity)
        }
    }

    // ================= Counter reset for graph replay =================
    __syncthreads();
    if (tid == 0) {
        const int old = atomicAdd(&g_done, 1);
        if (old == PB - 1) {
            #pragma unroll
            for (int s = 0; s < 8; s++) atomicExch(&g_arr[s << 5], 0);
            atomicExch(&g_done, 0);
        }
    }
}

extern "C" void kernel_launch(void* const* d_in, const int* in_sizes, int n_in,
                              void* d_out, int out_size) {
    const float* nullary = (const float*)d_in[0];  // (32, 64)
    const float* unary   = (const float*)d_in[1];  // (32, 8, 128)
    const float* binary  = (const float*)d_in[2];  // (32, 8, 7, 64)
    const float* kern    = (const float*)d_in[3];  // (448, 128)
    float* out = (float*)d_out;                    // (32, 128)

    fused_k<<<GRID, NT>>>(nullary, unary, binary, kern, out);
}